// round 2
// baseline (speedup 1.0000x reference)
#include <cuda_runtime.h>
#include <math.h>

#define B 64
#define L 2048
#define D 300
#define KW 111
#define NTOK (B*L)
#define SGLEN 2160   // 2048 + 2*55 + pad for k=111 dummy tap

// ---- device scratch (no allocs allowed) ----
__device__ float g0_scr[NTOK];
__device__ float g1_scr[NTOK];
__device__ float z_scr[B*D];
__device__ float cnorm_scr[2];

// ---------------------------------------------------------------------------
// Kernel 0: class-embedding norms (2 rows of 300)
// ---------------------------------------------------------------------------
__global__ void cnorm_kernel(const float* __restrict__ cls) {
    int w = threadIdx.x >> 5, lane = threadIdx.x & 31;
    if (w < 2) {
        float ss = 0.f;
        for (int d = lane; d < D; d += 32) { float v = cls[w*D + d]; ss += v*v; }
        #pragma unroll
        for (int o = 16; o > 0; o >>= 1) ss += __shfl_xor_sync(0xffffffffu, ss, o);
        if (lane == 0) cnorm_scr[w] = fmaxf(sqrtf(ss), 1e-12f);
    }
}

// ---------------------------------------------------------------------------
// Kernel 1: per-token gather + L2 norm + 2 class dots  (pass 1, ~157MB reads)
// one warp per token; 8 warps/block; grid = NTOK/8 exactly
// ---------------------------------------------------------------------------
__global__ void dot_kernel(const int* __restrict__ inputs,
                           const float* __restrict__ emb,
                           const float* __restrict__ cls) {
    __shared__ float sc[2*D];
    for (int i = threadIdx.x; i < 2*D; i += blockDim.x) sc[i] = cls[i];
    __syncthreads();

    int warp = threadIdx.x >> 5, lane = threadIdx.x & 31;
    int tok = blockIdx.x * 8 + warp;
    const float* row = emb + (size_t)inputs[tok] * D;

    float ss = 0.f, d0 = 0.f, d1 = 0.f;
    #pragma unroll
    for (int j = 0; j < 9; j++) {
        int d = lane + 32*j;
        float e = __ldg(row + d);
        ss += e*e; d0 += e*sc[d]; d1 += e*sc[D+d];
    }
    if (lane < 12) {                      // tail: 300 = 9*32 + 12
        int d = 288 + lane;
        float e = __ldg(row + d);
        ss += e*e; d0 += e*sc[d]; d1 += e*sc[D+d];
    }
    #pragma unroll
    for (int o = 16; o > 0; o >>= 1) {
        ss += __shfl_xor_sync(0xffffffffu, ss, o);
        d0 += __shfl_xor_sync(0xffffffffu, d0, o);
        d1 += __shfl_xor_sync(0xffffffffu, d1, o);
    }
    if (lane == 0) {
        float inv = 1.0f / fmaxf(sqrtf(ss), 1e-12f);
        g0_scr[tok] = d0 * inv / cnorm_scr[0];
        g1_scr[tok] = d1 * inv / cnorm_scr[1];
    }
}

// ---------------------------------------------------------------------------
// Kernel 2: conv1d(C=2->2, K=111, pad 55) + relu + channel-max + row softmax.
// One block (256 threads) per batch row; 8 positions/thread with a rolling
// register window so the K-loop is FMA-bound, not LDS-bound.
// Also zeroes z_scr[b] for kernel 3.
// ---------------------------------------------------------------------------
__global__ void conv_softmax_kernel(const float* __restrict__ conv_w,
                                    const float* __restrict__ conv_b,
                                    float* __restrict__ out, int beta_off) {
    __shared__ float sg0[SGLEN], sg1[SGLEN], sw[448], sred[256];
    int b = blockIdx.x, tid = threadIdx.x;

    for (int d = tid; d < D; d += 256) z_scr[b*D + d] = 0.f;   // for zacc
    for (int i = tid; i < SGLEN; i += 256) { sg0[i] = 0.f; sg1[i] = 0.f; }
    for (int t = tid; t < 448; t += 256) {                      // weights padded K=112
        int k = t % 112, ci = (t/112) & 1, o = t/224;
        sw[t] = (k < KW) ? conv_w[o*2*KW + ci*KW + k] : 0.f;
    }
    __syncthreads();
    for (int l = tid; l < L; l += 256) {
        sg0[55+l] = g0_scr[b*L + l];
        sg1[55+l] = g1_scr[b*L + l];
    }
    __syncthreads();

    float cb0 = __ldg(conv_b + 0), cb1 = __ldg(conv_b + 1);
    int l0 = tid * 8;
    float a0[8], a1[8], x0[8], x1[8];
    #pragma unroll
    for (int p = 0; p < 8; p++) {
        a0[p] = cb0; a1[p] = cb1;
        x0[p] = sg0[l0+p]; x1[p] = sg1[l0+p];
    }
    #pragma unroll 8
    for (int k = 0; k < 112; k++) {
        float w00 = sw[k], w01 = sw[112+k], w10 = sw[224+k], w11 = sw[336+k];
        #pragma unroll
        for (int p = 0; p < 8; p++) {
            float v0 = x0[(k+p)&7], v1 = x1[(k+p)&7];
            a0[p] += w00*v0 + w01*v1;
            a1[p] += w10*v0 + w11*v1;
        }
        x0[k&7] = sg0[l0+k+8];
        x1[k&7] = sg1[l0+k+8];
    }

    // s = max(relu(a0), relu(a1)) = max(0, a0, a1); then softmax over L
    float s[8]; float lmax = -1e30f;
    #pragma unroll
    for (int p = 0; p < 8; p++) {
        s[p] = fmaxf(0.f, fmaxf(a0[p], a1[p]));
        lmax = fmaxf(lmax, s[p]);
    }
    sred[tid] = lmax; __syncthreads();
    for (int st = 128; st > 0; st >>= 1) {
        if (tid < st) sred[tid] = fmaxf(sred[tid], sred[tid+st]);
        __syncthreads();
    }
    float m = sred[0]; __syncthreads();

    float lsum = 0.f;
    #pragma unroll
    for (int p = 0; p < 8; p++) { s[p] = expf(s[p]-m); lsum += s[p]; }
    sred[tid] = lsum; __syncthreads();
    for (int st = 128; st > 0; st >>= 1) {
        if (tid < st) sred[tid] += sred[tid+st];
        __syncthreads();
    }
    float inv = 1.0f / sred[0];

    float* bout = out + beta_off + b*L + l0;
    #pragma unroll
    for (int p = 0; p < 8; p++) bout[p] = s[p]*inv;
}

// ---------------------------------------------------------------------------
// Kernel 3: z[b,:] = sum_l beta[b,l] * emb_table[inputs[b,l]]  (pass 2)
// grid (64, 16): batch x 128-token chunk. 96 threads; rows are 1200B = 75
// float4 and 16B-aligned, so thread t covers float4 elements t and t+96
// (t+96 guarded by <75... i.e. only t<75-96<0 -> second covers none; instead
// split: t in [0,75) does one vec, and threads also cover remainder via a
// second strided slot). Layout: float4 index q in [0,75), covered by
// q = t (t<75) and nothing else -> we use 96 threads so 75 active vec lanes,
// remaining threads idle on loads but help staging.
// ---------------------------------------------------------------------------
__global__ void zacc_kernel(const int* __restrict__ inputs,
                            const float* __restrict__ emb,
                            const float* __restrict__ out, int beta_off) {
    __shared__ int   sidx[128];
    __shared__ float sb[128];
    int b = blockIdx.x, tid = threadIdx.x;
    int l0 = blockIdx.y * 128;
    if (tid < 128) {
        sidx[tid] = inputs[b*L + l0 + tid];
        sb[tid]   = out[beta_off + b*L + l0 + tid];
    }
    __syncthreads();

    // 96 threads, float4 element q = tid (q < 75 active)
    if (tid < 75) {
        float4 acc = make_float4(0.f, 0.f, 0.f, 0.f);
        #pragma unroll 4
        for (int t = 0; t < 128; t++) {
            const float4* row = (const float4*)(emb + (size_t)sidx[t] * D);
            float w = sb[t];
            float4 v = __ldg(row + tid);
            acc.x += w * v.x; acc.y += w * v.y;
            acc.z += w * v.z; acc.w += w * v.w;
        }
        float* zp = &z_scr[b*D + tid*4];
        atomicAdd(zp + 0, acc.x);
        atomicAdd(zp + 1, acc.y);
        atomicAdd(zp + 2, acc.z);
        atomicAdd(zp + 3, acc.w);
    }
}

// ---------------------------------------------------------------------------
// Kernel 4: logits = log_softmax(z @ lin_w^T + lin_b) over C=2
// one warp per batch row
// ---------------------------------------------------------------------------
__global__ void logits_kernel(const float* __restrict__ lin_w,
                              const float* __restrict__ lin_b,
                              float* __restrict__ out) {
    int b = blockIdx.x, lane = threadIdx.x;
    float o0 = 0.f, o1 = 0.f;
    for (int d = lane; d < D; d += 32) {
        float z = z_scr[b*D + d];
        o0 += z * __ldg(lin_w + d);
        o1 += z * __ldg(lin_w + D + d);
    }
    #pragma unroll
    for (int o = 16; o > 0; o >>= 1) {
        o0 += __shfl_xor_sync(0xffffffffu, o0, o);
        o1 += __shfl_xor_sync(0xffffffffu, o1, o);
    }
    if (lane == 0) {
        o0 += __ldg(lin_b + 0); o1 += __ldg(lin_b + 1);
        float m = fmaxf(o0, o1);
        float lse = m + logf(expf(o0 - m) + expf(o1 - m));
        out[b*2 + 0] = o0 - lse;
        out[b*2 + 1] = o1 - lse;
    }
}

// ---------------------------------------------------------------------------
extern "C" void kernel_launch(void* const* d_in, const int* in_sizes, int n_in,
                              void* d_out, int out_size) {
    const int*   inputs  = (const int*)  d_in[0];
    const float* emb     = (const float*)d_in[1];
    const float* cls     = (const float*)d_in[2];
    const float* conv_w  = (const float*)d_in[3];
    const float* conv_b  = (const float*)d_in[4];
    const float* lin_w   = (const float*)d_in[5];
    const float* lin_b   = (const float*)d_in[6];
    float* out = (float*)d_out;

    int beta_off = out_size - B*L;   // logits first, then beta [B,L]

    cnorm_kernel<<<1, 64>>>(cls);
    dot_kernel<<<NTOK/8, 256>>>(inputs, emb, cls);
    conv_softmax_kernel<<<B, 256>>>(conv_w, conv_b, out, beta_off);
    zacc_kernel<<<dim3(B, L/128), 128>>>(inputs, emb, out, beta_off);
    logits_kernel<<<B, 32>>>(lin_w, lin_b, out);
}

// round 3
// speedup vs baseline: 1.4246x; 1.4246x over previous
#include <cuda_runtime.h>
#include <math.h>

#define B 64
#define L 2048
#define D 300
#define KW 111
#define V 50000
#define NTOK (B*L)
#define SGLEN 2160       // 2048 + 2*55 + pad for k=111 dummy tap
#define NCHUNK 16        // token chunks per batch row in zacc
#define CTOK 128         // tokens per chunk

// ---- device scratch (no allocs allowed) ----
__device__ float2 vg_scr[V];                 // per-vocab normalized class dots
__device__ float  zpart_scr[B*NCHUNK*D];     // zacc partials (no atomics)

// ---------------------------------------------------------------------------
// Kernel 1: per-VOCAB-row normalized class dots (60MB streaming read).
// 8 warps/block, one warp per vocab row; float4 loads (row = 75 float4).
// Class norms computed redundantly per block (2 warps, trivial).
// ---------------------------------------------------------------------------
__global__ void vocab_dot_kernel(const float* __restrict__ emb,
                                 const float* __restrict__ cls) {
    __shared__ __align__(16) float sc[2*D];
    __shared__ float cninv[2];
    int tid = threadIdx.x, warp = tid >> 5, lane = tid & 31;

    for (int i = tid; i < 2*D; i += 256) sc[i] = cls[i];
    __syncthreads();
    if (warp < 2) {
        float ss = 0.f;
        for (int d = lane; d < D; d += 32) { float v = sc[warp*D + d]; ss += v*v; }
        #pragma unroll
        for (int o = 16; o > 0; o >>= 1) ss += __shfl_xor_sync(0xffffffffu, ss, o);
        if (lane == 0) cninv[warp] = 1.0f / fmaxf(sqrtf(ss), 1e-12f);
    }
    __syncthreads();

    int r = blockIdx.x * 8 + warp;           // vocab row (grid*8 == V exactly)
    const float4* row = (const float4*)(emb + (size_t)r * D);
    const float4* c0  = (const float4*)sc;
    const float4* c1  = (const float4*)(sc + D);

    float ss = 0.f, d0 = 0.f, d1 = 0.f;
    #pragma unroll
    for (int j = 0; j < 2; j++) {            // q = lane, lane+32
        int q = lane + 32*j;
        float4 e = __ldg(row + q);
        float4 a = c0[q], bq = c1[q];
        ss += e.x*e.x + e.y*e.y + e.z*e.z + e.w*e.w;
        d0 += e.x*a.x + e.y*a.y + e.z*a.z + e.w*a.w;
        d1 += e.x*bq.x + e.y*bq.y + e.z*bq.z + e.w*bq.w;
    }
    if (lane < 11) {                         // q = lane+64 (75 = 2*32 + 11)
        int q = lane + 64;
        float4 e = __ldg(row + q);
        float4 a = c0[q], bq = c1[q];
        ss += e.x*e.x + e.y*e.y + e.z*e.z + e.w*e.w;
        d0 += e.x*a.x + e.y*a.y + e.z*a.z + e.w*a.w;
        d1 += e.x*bq.x + e.y*bq.y + e.z*bq.z + e.w*bq.w;
    }
    #pragma unroll
    for (int o = 16; o > 0; o >>= 1) {
        ss += __shfl_xor_sync(0xffffffffu, ss, o);
        d0 += __shfl_xor_sync(0xffffffffu, d0, o);
        d1 += __shfl_xor_sync(0xffffffffu, d1, o);
    }
    if (lane == 0) {
        float inv = 1.0f / fmaxf(sqrtf(ss), 1e-12f);
        vg_scr[r] = make_float2(d0 * inv * cninv[0], d1 * inv * cninv[1]);
    }
}

// ---------------------------------------------------------------------------
// Kernel 2: gather vg by token + conv1d(2->2,K=111,pad55) + relu + channel-max
//           + row softmax -> beta. One block (256 thr) per batch row.
// ---------------------------------------------------------------------------
__global__ void conv_softmax_kernel(const int* __restrict__ inputs,
                                    const float* __restrict__ conv_w,
                                    const float* __restrict__ conv_b,
                                    float* __restrict__ out, int beta_off) {
    __shared__ float sg0[SGLEN], sg1[SGLEN], sw[448], sred[256];
    int b = blockIdx.x, tid = threadIdx.x;

    for (int i = tid; i < SGLEN; i += 256) { sg0[i] = 0.f; sg1[i] = 0.f; }
    for (int t = tid; t < 448; t += 256) {                 // weights padded K=112
        int k = t % 112, ci = (t/112) & 1, o = t/224;
        sw[t] = (k < KW) ? conv_w[o*2*KW + ci*KW + k] : 0.f;
    }
    __syncthreads();
    for (int l = tid; l < L; l += 256) {
        int v = inputs[b*L + l];
        float2 g = __ldg(&vg_scr[v]);
        sg0[55+l] = g.x;
        sg1[55+l] = g.y;
    }
    __syncthreads();

    float cb0 = __ldg(conv_b + 0), cb1 = __ldg(conv_b + 1);
    int l0 = tid * 8;
    float a0[8], a1[8], x0[8], x1[8];
    #pragma unroll
    for (int p = 0; p < 8; p++) {
        a0[p] = cb0; a1[p] = cb1;
        x0[p] = sg0[l0+p]; x1[p] = sg1[l0+p];
    }
    #pragma unroll 8
    for (int k = 0; k < 112; k++) {
        float w00 = sw[k], w01 = sw[112+k], w10 = sw[224+k], w11 = sw[336+k];
        #pragma unroll
        for (int p = 0; p < 8; p++) {
            float v0 = x0[(k+p)&7], v1 = x1[(k+p)&7];
            a0[p] += w00*v0 + w01*v1;
            a1[p] += w10*v0 + w11*v1;
        }
        x0[k&7] = sg0[l0+k+8];
        x1[k&7] = sg1[l0+k+8];
    }

    float s[8]; float lmax = -1e30f;
    #pragma unroll
    for (int p = 0; p < 8; p++) {
        s[p] = fmaxf(0.f, fmaxf(a0[p], a1[p]));   // max(relu(a0),relu(a1))
        lmax = fmaxf(lmax, s[p]);
    }
    sred[tid] = lmax; __syncthreads();
    for (int st = 128; st > 0; st >>= 1) {
        if (tid < st) sred[tid] = fmaxf(sred[tid], sred[tid+st]);
        __syncthreads();
    }
    float m = sred[0]; __syncthreads();

    float lsum = 0.f;
    #pragma unroll
    for (int p = 0; p < 8; p++) { s[p] = expf(s[p]-m); lsum += s[p]; }
    sred[tid] = lsum; __syncthreads();
    for (int st = 128; st > 0; st >>= 1) {
        if (tid < st) sred[tid] += sred[tid+st];
        __syncthreads();
    }
    float inv = 1.0f / sred[0];

    float* bout = out + beta_off + b*L + l0;
    #pragma unroll
    for (int p = 0; p < 8; p++) bout[p] = s[p]*inv;
}

// ---------------------------------------------------------------------------
// Kernel 3: zpart[b,chunk,:] = sum_{l in chunk} beta[b,l]*emb[inputs[b,l]]
// grid (64,16), 608 threads = 8 groups x 75 float4 lanes (all active).
// Each thread: 16 independent float4 loads (MLP=16). Cross-group reduce in
// shared, vectorized partial store. No atomics -> deterministic.
// ---------------------------------------------------------------------------
__global__ void zacc_kernel(const int* __restrict__ inputs,
                            const float* __restrict__ emb,
                            const float* __restrict__ out, int beta_off) {
    __shared__ int   sidx[CTOK];
    __shared__ float sb[CTOK];
    __shared__ __align__(16) float4 sacc[8][75];
    int b = blockIdx.x, chunk = blockIdx.y, tid = threadIdx.x;
    int l0 = chunk * CTOK;
    if (tid < CTOK) {
        sidx[tid] = inputs[b*L + l0 + tid];
        sb[tid]   = out[beta_off + b*L + l0 + tid];
    }
    __syncthreads();

    int g = tid / 75;              // group 0..7 (tid<600), rest idle
    int q = tid - g * 75;          // float4 lane 0..74
    if (g < 8) {
        float4 acc = make_float4(0.f, 0.f, 0.f, 0.f);
        int t0 = g * 16;
        #pragma unroll
        for (int i = 0; i < 16; i++) {
            int t = t0 + i;
            const float4* row = (const float4*)(emb + (size_t)sidx[t] * D);
            float w = sb[t];
            float4 v = __ldg(row + q);
            acc.x += w*v.x; acc.y += w*v.y; acc.z += w*v.z; acc.w += w*v.w;
        }
        sacc[g][q] = acc;
    }
    __syncthreads();

    if (tid < 75) {
        float4 s = make_float4(0.f, 0.f, 0.f, 0.f);
        #pragma unroll
        for (int gg = 0; gg < 8; gg++) {
            float4 a = sacc[gg][tid];
            s.x += a.x; s.y += a.y; s.z += a.z; s.w += a.w;
        }
        ((float4*)&zpart_scr[(b*NCHUNK + chunk) * D])[tid] = s;
    }
}

// ---------------------------------------------------------------------------
// Kernel 4: reduce zpart over chunks, then logits = log_softmax(z@W^T + b).
// One block (512 thr) per batch row.
// ---------------------------------------------------------------------------
__global__ void logits_kernel(const float* __restrict__ lin_w,
                              const float* __restrict__ lin_b,
                              float* __restrict__ out) {
    __shared__ float sr0[512], sr1[512];
    int b = blockIdx.x, tid = threadIdx.x;
    float o0 = 0.f, o1 = 0.f;
    if (tid < D) {
        float z = 0.f;
        #pragma unroll
        for (int c = 0; c < NCHUNK; c++)
            z += zpart_scr[(b*NCHUNK + c) * D + tid];
        o0 = z * __ldg(lin_w + tid);
        o1 = z * __ldg(lin_w + D + tid);
    }
    sr0[tid] = o0; sr1[tid] = o1; __syncthreads();
    for (int st = 256; st > 0; st >>= 1) {
        if (tid < st) { sr0[tid] += sr0[tid+st]; sr1[tid] += sr1[tid+st]; }
        __syncthreads();
    }
    if (tid == 0) {
        float a = sr0[0] + __ldg(lin_b + 0);
        float c = sr1[0] + __ldg(lin_b + 1);
        float m = fmaxf(a, c);
        float lse = m + logf(expf(a - m) + expf(c - m));
        out[b*2 + 0] = a - lse;
        out[b*2 + 1] = c - lse;
    }
}

// ---------------------------------------------------------------------------
extern "C" void kernel_launch(void* const* d_in, const int* in_sizes, int n_in,
                              void* d_out, int out_size) {
    const int*   inputs  = (const int*)  d_in[0];
    const float* emb     = (const float*)d_in[1];
    const float* cls     = (const float*)d_in[2];
    const float* conv_w  = (const float*)d_in[3];
    const float* conv_b  = (const float*)d_in[4];
    const float* lin_w   = (const float*)d_in[5];
    const float* lin_b   = (const float*)d_in[6];
    float* out = (float*)d_out;

    int beta_off = out_size - B*L;   // logits first, then beta [B,L]

    vocab_dot_kernel<<<V/8, 256>>>(emb, cls);                       // 6250 blocks
    conv_softmax_kernel<<<B, 256>>>(inputs, conv_w, conv_b, out, beta_off);
    zacc_kernel<<<dim3(B, NCHUNK), 608>>>(inputs, emb, out, beta_off);
    logits_kernel<<<B, 512>>>(lin_w, lin_b, out);
}

// round 4
// speedup vs baseline: 1.6611x; 1.1660x over previous
#include <cuda_runtime.h>
#include <math.h>

#define B 64
#define L 2048
#define D 300
#define KW 111
#define V 50000
#define NCHUNK 16        // token chunks per batch row in zacc
#define CTOK 128         // tokens per chunk
#define HL 1024          // conv half-length per block
#define SG2 1140         // halo'd shared length: 1024 + 111 + 4 + pad

// ---- device scratch (no allocs allowed) ----
__device__ float2 vg_scr[V];                 // per-vocab normalized class dots
__device__ float  zpart_scr[B*NCHUNK*D];     // zacc partials (no atomics)
__device__ float  esum_scr[B*2];             // per-half exp-sum partials

// ---------------------------------------------------------------------------
// Kernel 1: per-VOCAB-row normalized class dots (60MB streaming read).
// 8 warps/block, TWO rows per warp (6 independent 512B loads in flight).
// ---------------------------------------------------------------------------
__global__ void vocab_dot_kernel(const float* __restrict__ emb,
                                 const float* __restrict__ cls) {
    __shared__ __align__(16) float sc[2*D];
    __shared__ float cninv[2];
    int tid = threadIdx.x, warp = tid >> 5, lane = tid & 31;

    for (int i = tid; i < 2*D; i += 256) sc[i] = cls[i];
    __syncthreads();
    if (warp < 2) {
        float ss = 0.f;
        for (int d = lane; d < D; d += 32) { float v = sc[warp*D + d]; ss += v*v; }
        #pragma unroll
        for (int o = 16; o > 0; o >>= 1) ss += __shfl_xor_sync(0xffffffffu, ss, o);
        if (lane == 0) cninv[warp] = 1.0f / fmaxf(sqrtf(ss), 1e-12f);
    }
    __syncthreads();

    const float4* c0 = (const float4*)sc;
    const float4* c1 = (const float4*)(sc + D);
    int rbase = blockIdx.x * 16 + warp * 2;          // grid*16 == V exactly

    #pragma unroll
    for (int rr = 0; rr < 2; rr++) {
        int r = rbase + rr;
        const float4* row = (const float4*)(emb + (size_t)r * D);
        // issue all three loads up front (independent)
        float4 e0 = __ldg(row + lane);
        float4 e1 = __ldg(row + lane + 32);
        float4 e2 = (lane < 11) ? __ldg(row + lane + 64)
                                : make_float4(0.f, 0.f, 0.f, 0.f);
        float ss = 0.f, d0 = 0.f, d1 = 0.f;
        {
            int q = lane;           float4 a = c0[q], bq = c1[q];
            ss += e0.x*e0.x + e0.y*e0.y + e0.z*e0.z + e0.w*e0.w;
            d0 += e0.x*a.x + e0.y*a.y + e0.z*a.z + e0.w*a.w;
            d1 += e0.x*bq.x + e0.y*bq.y + e0.z*bq.z + e0.w*bq.w;
        }
        {
            int q = lane + 32;      float4 a = c0[q], bq = c1[q];
            ss += e1.x*e1.x + e1.y*e1.y + e1.z*e1.z + e1.w*e1.w;
            d0 += e1.x*a.x + e1.y*a.y + e1.z*a.z + e1.w*a.w;
            d1 += e1.x*bq.x + e1.y*bq.y + e1.z*bq.z + e1.w*bq.w;
        }
        if (lane < 11) {
            int q = lane + 64;      float4 a = c0[q], bq = c1[q];
            ss += e2.x*e2.x + e2.y*e2.y + e2.z*e2.z + e2.w*e2.w;
            d0 += e2.x*a.x + e2.y*a.y + e2.z*a.z + e2.w*a.w;
            d1 += e2.x*bq.x + e2.y*bq.y + e2.z*bq.z + e2.w*bq.w;
        }
        #pragma unroll
        for (int o = 16; o > 0; o >>= 1) {
            ss += __shfl_xor_sync(0xffffffffu, ss, o);
            d0 += __shfl_xor_sync(0xffffffffu, d0, o);
            d1 += __shfl_xor_sync(0xffffffffu, d1, o);
        }
        if (lane == 0) {
            float inv = 1.0f / fmaxf(sqrtf(ss), 1e-12f);
            vg_scr[r] = make_float2(d0 * inv * cninv[0], d1 * inv * cninv[1]);
        }
    }
}

// ---------------------------------------------------------------------------
// Kernel 2: gather vg + conv1d(2->2,K=111,pad55) + relu + channel-max + exp.
// grid (B, 2): each block handles 1024 positions (+55 halo each side).
// Writes UNNORMALIZED e=exp(s) to the beta slot and a per-half sum to scratch.
// (No max-subtraction: s <= sum|w| < 35, exp cannot overflow fp32; the
//  normalized ratio is mathematically identical to the max-subtracted form.)
// ---------------------------------------------------------------------------
__global__ void conv_exp_kernel(const int* __restrict__ inputs,
                                const float* __restrict__ vg_dummy,
                                const float* __restrict__ conv_w,
                                const float* __restrict__ conv_b,
                                float* __restrict__ out, int beta_off) {
    __shared__ float sg0[SG2], sg1[SG2], sw[448], sred[256];
    int b = blockIdx.x, half = blockIdx.y, tid = threadIdx.x;
    int l0 = half * HL;

    for (int i = tid; i < SG2; i += 256) { sg0[i] = 0.f; sg1[i] = 0.f; }
    for (int t = tid; t < 448; t += 256) {                 // weights padded K=112
        int k = t % 112, ci = (t/112) & 1, o = t/224;
        sw[t] = (k < KW) ? conv_w[o*2*KW + ci*KW + k] : 0.f;
    }
    __syncthreads();
    // sg[i] corresponds to global position l0 - 55 + i
    for (int i = tid; i < HL + 111; i += 256) {
        int gl = l0 - 55 + i;
        if (gl >= 0 && gl < L) {
            float2 g = __ldg(&vg_scr[inputs[b*L + gl]]);
            sg0[i] = g.x; sg1[i] = g.y;
        }
    }
    __syncthreads();

    float cb0 = __ldg(conv_b + 0), cb1 = __ldg(conv_b + 1);
    int lp0 = tid * 4;                                     // local position base
    float a0[4], a1[4], x0[4], x1[4];
    #pragma unroll
    for (int p = 0; p < 4; p++) {
        a0[p] = cb0; a1[p] = cb1;
        x0[p] = sg0[lp0+p]; x1[p] = sg1[lp0+p];
    }
    #pragma unroll 8
    for (int k = 0; k < 112; k++) {
        float w00 = sw[k], w01 = sw[112+k], w10 = sw[224+k], w11 = sw[336+k];
        #pragma unroll
        for (int p = 0; p < 4; p++) {
            float v0 = x0[(k+p)&3], v1 = x1[(k+p)&3];
            a0[p] += w00*v0 + w01*v1;
            a1[p] += w10*v0 + w11*v1;
        }
        x0[k&3] = sg0[lp0+k+4];
        x1[k&3] = sg1[lp0+k+4];
    }

    float e[4]; float lsum = 0.f;
    #pragma unroll
    for (int p = 0; p < 4; p++) {
        float s = fmaxf(0.f, fmaxf(a0[p], a1[p]));   // max(relu(a0),relu(a1))
        e[p] = expf(s);
        lsum += e[p];
    }
    float* bout = out + beta_off + b*L + l0 + lp0;
    #pragma unroll
    for (int p = 0; p < 4; p++) bout[p] = e[p];

    sred[tid] = lsum; __syncthreads();
    for (int st = 128; st > 0; st >>= 1) {
        if (tid < st) sred[tid] += sred[tid+st];
        __syncthreads();
    }
    if (tid == 0) esum_scr[b*2 + half] = sred[0];
}

// ---------------------------------------------------------------------------
// Kernel 3: zpart[b,chunk,:] = sum_{l in chunk} beta[b,l]*emb[inputs[b,l]]
// Normalizes beta on the fly (w = e * invsum) and writes normalized beta back
// in-place (each element exactly once). 608 thr = 8 groups x 75 float4 lanes.
// ---------------------------------------------------------------------------
__global__ void zacc_kernel(const int* __restrict__ inputs,
                            const float* __restrict__ emb,
                            float* __restrict__ out, int beta_off) {
    __shared__ int   sidx[CTOK];
    __shared__ float sb[CTOK];
    __shared__ __align__(16) float4 sacc[8][75];
    int b = blockIdx.x, chunk = blockIdx.y, tid = threadIdx.x;
    int l0 = chunk * CTOK;
    float invsum = 1.0f / (esum_scr[b*2] + esum_scr[b*2+1]);
    if (tid < CTOK) {
        sidx[tid] = inputs[b*L + l0 + tid];
        float w = out[beta_off + b*L + l0 + tid] * invsum;
        sb[tid] = w;
        out[beta_off + b*L + l0 + tid] = w;     // normalized beta, final
    }
    __syncthreads();

    int g = tid / 75;              // group 0..7 (tid<600), rest idle
    int q = tid - g * 75;          // float4 lane 0..74
    if (g < 8) {
        float4 acc = make_float4(0.f, 0.f, 0.f, 0.f);
        int t0 = g * 16;
        #pragma unroll
        for (int i = 0; i < 16; i++) {
            int t = t0 + i;
            const float4* row = (const float4*)(emb + (size_t)sidx[t] * D);
            float w = sb[t];
            float4 v = __ldg(row + q);
            acc.x += w*v.x; acc.y += w*v.y; acc.z += w*v.z; acc.w += w*v.w;
        }
        sacc[g][q] = acc;
    }
    __syncthreads();

    if (tid < 75) {
        float4 s = make_float4(0.f, 0.f, 0.f, 0.f);
        #pragma unroll
        for (int gg = 0; gg < 8; gg++) {
            float4 a = sacc[gg][tid];
            s.x += a.x; s.y += a.y; s.z += a.z; s.w += a.w;
        }
        ((float4*)&zpart_scr[(b*NCHUNK + chunk) * D])[tid] = s;
    }
}

// ---------------------------------------------------------------------------
// Kernel 4: reduce zpart over chunks + logits = log_softmax(z@W^T + b).
// 128 threads/row: 75 float4 lanes, 16 coalesced chunk loads each.
// ---------------------------------------------------------------------------
__global__ void logits_kernel(const float* __restrict__ lin_w,
                              const float* __restrict__ lin_b,
                              float* __restrict__ out) {
    __shared__ float sr0[128], sr1[128];
    int b = blockIdx.x, tid = threadIdx.x;
    float o0 = 0.f, o1 = 0.f;
    if (tid < 75) {
        float4 z = make_float4(0.f, 0.f, 0.f, 0.f);
        #pragma unroll
        for (int c = 0; c < NCHUNK; c++) {
            float4 p = ((const float4*)&zpart_scr[(b*NCHUNK + c) * D])[tid];
            z.x += p.x; z.y += p.y; z.z += p.z; z.w += p.w;
        }
        float4 w0 = __ldg((const float4*)lin_w + tid);
        float4 w1 = __ldg((const float4*)(lin_w + D) + tid);
        o0 = z.x*w0.x + z.y*w0.y + z.z*w0.z + z.w*w0.w;
        o1 = z.x*w1.x + z.y*w1.y + z.z*w1.z + z.w*w1.w;
    }
    sr0[tid] = o0; sr1[tid] = o1; __syncthreads();
    for (int st = 64; st > 0; st >>= 1) {
        if (tid < st) { sr0[tid] += sr0[tid+st]; sr1[tid] += sr1[tid+st]; }
        __syncthreads();
    }
    if (tid == 0) {
        float a = sr0[0] + __ldg(lin_b + 0);
        float c = sr1[0] + __ldg(lin_b + 1);
        float m = fmaxf(a, c);
        float lse = m + logf(expf(a - m) + expf(c - m));
        out[b*2 + 0] = a - lse;
        out[b*2 + 1] = c - lse;
    }
}

// ---------------------------------------------------------------------------
extern "C" void kernel_launch(void* const* d_in, const int* in_sizes, int n_in,
                              void* d_out, int out_size) {
    const int*   inputs  = (const int*)  d_in[0];
    const float* emb     = (const float*)d_in[1];
    const float* cls     = (const float*)d_in[2];
    const float* conv_w  = (const float*)d_in[3];
    const float* conv_b  = (const float*)d_in[4];
    const float* lin_w   = (const float*)d_in[5];
    const float* lin_b   = (const float*)d_in[6];
    float* out = (float*)d_out;

    int beta_off = out_size - B*L;   // logits first, then beta [B,L]

    vocab_dot_kernel<<<V/16, 256>>>(emb, cls);                       // 3125 blocks
    conv_exp_kernel<<<dim3(B, 2), 256>>>(inputs, nullptr, conv_w, conv_b, out, beta_off);
    zacc_kernel<<<dim3(B, NCHUNK), 608>>>(inputs, emb, out, beta_off);
    logits_kernel<<<B, 128>>>(lin_w, lin_b, out);
}

// round 6
// speedup vs baseline: 1.7623x; 1.0609x over previous
#include <cuda_runtime.h>
#include <math.h>

#define B 64
#define L 2048
#define D 300
#define KW 111
#define V 50000
#define NCHUNK 8         // token chunks per batch row in zacc
#define CTOK 256         // tokens per chunk
#define HL 1024          // conv half-length per block
#define SG2 1140         // halo'd shared length: 1024 + 111 + 4 + pad

// ---- device scratch (no allocs allowed) ----
__device__ float2 vg_scr[V];                 // per-vocab normalized class dots
__device__ float  zpart_scr[B*NCHUNK*D];     // zacc partials (no atomics)
__device__ float  esum_scr[B*2];             // per-half exp-sum partials

// ---------------------------------------------------------------------------
// Kernel 1: per-VOCAB-row normalized class dots (60MB streaming read).
// 8 warps/block, TWO rows per warp; all 6 row-loads issued up front, then one
// combined 6-value butterfly reduction (max MLP + shuffle ILP).
// ---------------------------------------------------------------------------
__global__ void vocab_dot_kernel(const float* __restrict__ emb,
                                 const float* __restrict__ cls) {
    __shared__ __align__(16) float sc[2*D];
    __shared__ float cninv[2];
    int tid = threadIdx.x, warp = tid >> 5, lane = tid & 31;

    for (int i = tid; i < 2*D; i += 256) sc[i] = cls[i];
    __syncthreads();
    if (warp < 2) {
        float ss = 0.f;
        for (int d = lane; d < D; d += 32) { float v = sc[warp*D + d]; ss += v*v; }
        #pragma unroll
        for (int o = 16; o > 0; o >>= 1) ss += __shfl_xor_sync(0xffffffffu, ss, o);
        if (lane == 0) cninv[warp] = 1.0f / fmaxf(sqrtf(ss), 1e-12f);
    }
    __syncthreads();

    const float4* c0 = (const float4*)sc;
    const float4* c1 = (const float4*)(sc + D);
    int r = blockIdx.x * 16 + warp * 2;              // grid*16 == V exactly

    const float4* rowA = (const float4*)(emb + (size_t)r * D);
    const float4* rowB = (const float4*)(emb + (size_t)(r+1) * D);
    bool tail = (lane < 11);
    float4 zf = make_float4(0.f,0.f,0.f,0.f);
    // issue all 6 loads before any math
    float4 A0 = __ldg(rowA + lane);
    float4 A1 = __ldg(rowA + lane + 32);
    float4 A2 = tail ? __ldg(rowA + lane + 64) : zf;
    float4 B0 = __ldg(rowB + lane);
    float4 B1 = __ldg(rowB + lane + 32);
    float4 B2 = tail ? __ldg(rowB + lane + 64) : zf;

    float ssA=0.f, dA0=0.f, dA1=0.f, ssB=0.f, dB0=0.f, dB1=0.f;
    {
        float4 a = c0[lane], bq = c1[lane];
        ssA += A0.x*A0.x + A0.y*A0.y + A0.z*A0.z + A0.w*A0.w;
        dA0 += A0.x*a.x + A0.y*a.y + A0.z*a.z + A0.w*a.w;
        dA1 += A0.x*bq.x + A0.y*bq.y + A0.z*bq.z + A0.w*bq.w;
        ssB += B0.x*B0.x + B0.y*B0.y + B0.z*B0.z + B0.w*B0.w;
        dB0 += B0.x*a.x + B0.y*a.y + B0.z*a.z + B0.w*a.w;
        dB1 += B0.x*bq.x + B0.y*bq.y + B0.z*bq.z + B0.w*bq.w;
    }
    {
        float4 a = c0[lane+32], bq = c1[lane+32];
        ssA += A1.x*A1.x + A1.y*A1.y + A1.z*A1.z + A1.w*A1.w;
        dA0 += A1.x*a.x + A1.y*a.y + A1.z*a.z + A1.w*a.w;
        dA1 += A1.x*bq.x + A1.y*bq.y + A1.z*bq.z + A1.w*bq.w;
        ssB += B1.x*B1.x + B1.y*B1.y + B1.z*B1.z + B1.w*B1.w;
        dB0 += B1.x*a.x + B1.y*a.y + B1.z*a.z + B1.w*a.w;
        dB1 += B1.x*bq.x + B1.y*bq.y + B1.z*bq.z + B1.w*bq.w;
    }
    if (tail) {
        float4 a = c0[lane+64], bq = c1[lane+64];
        ssA += A2.x*A2.x + A2.y*A2.y + A2.z*A2.z + A2.w*A2.w;
        dA0 += A2.x*a.x + A2.y*a.y + A2.z*a.z + A2.w*a.w;
        dA1 += A2.x*bq.x + A2.y*bq.y + A2.z*bq.z + A2.w*bq.w;
        ssB += B2.x*B2.x + B2.y*B2.y + B2.z*B2.z + B2.w*B2.w;
        dB0 += B2.x*a.x + B2.y*a.y + B2.z*a.z + B2.w*a.w;
        dB1 += B2.x*bq.x + B2.y*bq.y + B2.z*bq.z + B2.w*bq.w;
    }
    #pragma unroll
    for (int o = 16; o > 0; o >>= 1) {
        ssA += __shfl_xor_sync(0xffffffffu, ssA, o);
        dA0 += __shfl_xor_sync(0xffffffffu, dA0, o);
        dA1 += __shfl_xor_sync(0xffffffffu, dA1, o);
        ssB += __shfl_xor_sync(0xffffffffu, ssB, o);
        dB0 += __shfl_xor_sync(0xffffffffu, dB0, o);
        dB1 += __shfl_xor_sync(0xffffffffu, dB1, o);
    }
    if (lane == 0) {
        float invA = 1.0f / fmaxf(sqrtf(ssA), 1e-12f);
        float invB = 1.0f / fmaxf(sqrtf(ssB), 1e-12f);
        vg_scr[r]   = make_float2(dA0 * invA * cninv[0], dA1 * invA * cninv[1]);
        vg_scr[r+1] = make_float2(dB0 * invB * cninv[0], dB1 * invB * cninv[1]);
    }
}

// ---------------------------------------------------------------------------
// Kernel 2: gather vg + conv1d(2->2,K=111,pad55) + relu + channel-max + exp.
// grid (B, 2): each block handles 1024 positions (+55 halo each side).
// Writes UNNORMALIZED e=exp(s) to beta slot + per-half sum to scratch.
// (s <= sum|w|*|g| stays small; exp cannot overflow fp32; ratio identical to
//  max-subtracted softmax.)
// ---------------------------------------------------------------------------
__global__ void conv_exp_kernel(const int* __restrict__ inputs,
                                const float* __restrict__ conv_w,
                                const float* __restrict__ conv_b,
                                float* __restrict__ out, int beta_off) {
    __shared__ float sg0[SG2], sg1[SG2], sw[448], sred[256];
    int b = blockIdx.x, half = blockIdx.y, tid = threadIdx.x;
    int l0 = half * HL;

    for (int i = tid; i < SG2; i += 256) { sg0[i] = 0.f; sg1[i] = 0.f; }
    for (int t = tid; t < 448; t += 256) {                 // weights padded K=112
        int k = t % 112, ci = (t/112) & 1, o = t/224;
        sw[t] = (k < KW) ? conv_w[o*2*KW + ci*KW + k] : 0.f;
    }
    __syncthreads();
    // sg[i] corresponds to global position l0 - 55 + i
    for (int i = tid; i < HL + 111; i += 256) {
        int gl = l0 - 55 + i;
        if (gl >= 0 && gl < L) {
            float2 g = __ldg(&vg_scr[inputs[b*L + gl]]);
            sg0[i] = g.x; sg1[i] = g.y;
        }
    }
    __syncthreads();

    float cb0 = __ldg(conv_b + 0), cb1 = __ldg(conv_b + 1);
    int lp0 = tid * 4;                                     // local position base
    float a0[4], a1[4], x0[4], x1[4];
    #pragma unroll
    for (int p = 0; p < 4; p++) {
        a0[p] = cb0; a1[p] = cb1;
        x0[p] = sg0[lp0+p]; x1[p] = sg1[lp0+p];
    }
    #pragma unroll 8
    for (int k = 0; k < 112; k++) {
        float w00 = sw[k], w01 = sw[112+k], w10 = sw[224+k], w11 = sw[336+k];
        #pragma unroll
        for (int p = 0; p < 4; p++) {
            float v0 = x0[(k+p)&3], v1 = x1[(k+p)&3];
            a0[p] += w00*v0 + w01*v1;
            a1[p] += w10*v0 + w11*v1;
        }
        x0[k&3] = sg0[lp0+k+4];
        x1[k&3] = sg1[lp0+k+4];
    }

    float e[4]; float lsum = 0.f;
    #pragma unroll
    for (int p = 0; p < 4; p++) {
        float s = fmaxf(0.f, fmaxf(a0[p], a1[p]));   // max(relu(a0),relu(a1))
        e[p] = expf(s);
        lsum += e[p];
    }
    float* bout = out + beta_off + b*L + l0 + lp0;
    #pragma unroll
    for (int p = 0; p < 4; p++) bout[p] = e[p];

    sred[tid] = lsum; __syncthreads();
    for (int st = 128; st > 0; st >>= 1) {
        if (tid < st) sred[tid] += sred[tid+st];
        __syncthreads();
    }
    if (tid == 0) esum_scr[b*2 + half] = sred[0];
}

// ---------------------------------------------------------------------------
// Kernel 3: zpart[b,chunk,:] = sum_{l in chunk} beta[b,l]*emb[inputs[b,l]]
// grid (64, 8) -> ~1.15 waves at 3 blocks/SM. 608 thr = 8 groups x 75 float4
// lanes; each group accumulates 32 tokens (unroll 8 => MLP 8/thread).
// Normalizes beta on the fly and writes normalized beta back in-place.
// ---------------------------------------------------------------------------
__global__ void zacc_kernel(const int* __restrict__ inputs,
                            const float* __restrict__ emb,
                            float* __restrict__ out, int beta_off) {
    __shared__ int   sidx[CTOK];
    __shared__ float sb[CTOK];
    __shared__ __align__(16) float4 sacc[8][75];
    int b = blockIdx.x, chunk = blockIdx.y, tid = threadIdx.x;
    int l0 = chunk * CTOK;
    float invsum = 1.0f / (esum_scr[b*2] + esum_scr[b*2+1]);
    if (tid < CTOK) {
        sidx[tid] = inputs[b*L + l0 + tid];
        float w = out[beta_off + b*L + l0 + tid] * invsum;
        sb[tid] = w;
        out[beta_off + b*L + l0 + tid] = w;     // normalized beta, final
    }
    __syncthreads();

    int g = tid / 75;              // group 0..7 (tid<600), rest idle
    int q = tid - g * 75;          // float4 lane 0..74
    if (g < 8) {
        float4 acc = make_float4(0.f, 0.f, 0.f, 0.f);
        int t0 = g * 32;
        #pragma unroll 8
        for (int i = 0; i < 32; i++) {
            int t = t0 + i;
            const float4* row = (const float4*)(emb + (size_t)sidx[t] * D);
            float w = sb[t];
            float4 v = __ldg(row + q);
            acc.x += w*v.x; acc.y += w*v.y; acc.z += w*v.z; acc.w += w*v.w;
        }
        sacc[g][q] = acc;
    }
    __syncthreads();

    if (tid < 75) {
        float4 s = make_float4(0.f, 0.f, 0.f, 0.f);
        #pragma unroll
        for (int gg = 0; gg < 8; gg++) {
            float4 a = sacc[gg][tid];
            s.x += a.x; s.y += a.y; s.z += a.z; s.w += a.w;
        }
        ((float4*)&zpart_scr[(b*NCHUNK + chunk) * D])[tid] = s;
    }
}

// ---------------------------------------------------------------------------
// Kernel 4: reduce zpart over chunks + logits = log_softmax(z@W^T + b).
// 608 thr: 8 groups x 75 lanes, one chunk per group (single float4 load each),
// shared cross-group reduce, then 75-lane dot + tree.
// ---------------------------------------------------------------------------
__global__ void logits_kernel(const float* __restrict__ lin_w,
                              const float* __restrict__ lin_b,
                              float* __restrict__ out) {
    __shared__ __align__(16) float4 sz[8][75];
    __shared__ float sr0[128], sr1[128];
    int b = blockIdx.x, tid = threadIdx.x;
    int g = tid / 75, q = tid - g * 75;
    if (g < 8)
        sz[g][q] = ((const float4*)&zpart_scr[(b*NCHUNK + g) * D])[q];
    __syncthreads();

    if (tid < 128) { sr0[tid] = 0.f; sr1[tid] = 0.f; }
    __syncthreads();
    if (tid < 75) {
        float4 z = make_float4(0.f, 0.f, 0.f, 0.f);
        #pragma unroll
        for (int gg = 0; gg < 8; gg++) {
            float4 p = sz[gg][tid];
            z.x += p.x; z.y += p.y; z.z += p.z; z.w += p.w;
        }
        float4 w0 = __ldg((const float4*)lin_w + tid);
        float4 w1 = __ldg((const float4*)(lin_w + D) + tid);
        sr0[tid] = z.x*w0.x + z.y*w0.y + z.z*w0.z + z.w*w0.w;
        sr1[tid] = z.x*w1.x + z.y*w1.y + z.z*w1.z + z.w*w1.w;
    }
    __syncthreads();
    for (int st = 64; st > 0; st >>= 1) {
        if (tid < st) { sr0[tid] += sr0[tid+st]; sr1[tid] += sr1[tid+st]; }
        __syncthreads();
    }
    if (tid == 0) {
        float a = sr0[0] + __ldg(lin_b + 0);
        float c = sr1[0] + __ldg(lin_b + 1);
        float m = fmaxf(a, c);
        float lse = m + logf(expf(a - m) + expf(c - m));
        out[b*2 + 0] = a - lse;
        out[b*2 + 1] = c - lse;
    }
}

// ---------------------------------------------------------------------------
extern "C" void kernel_launch(void* const* d_in, const int* in_sizes, int n_in,
                              void* d_out, int out_size) {
    const int*   inputs  = (const int*)  d_in[0];
    const float* emb     = (const float*)d_in[1];
    const float* cls     = (const float*)d_in[2];
    const float* conv_w  = (const float*)d_in[3];
    const float* conv_b  = (const float*)d_in[4];
    const float* lin_w   = (const float*)d_in[5];
    const float* lin_b   = (const float*)d_in[6];
    float* out = (float*)d_out;

    int beta_off = out_size - B*L;   // logits first, then beta [B,L]

    vocab_dot_kernel<<<V/16, 256>>>(emb, cls);                       // 3125 blocks
    conv_exp_kernel<<<dim3(B, 2), 256>>>(inputs, conv_w, conv_b, out, beta_off);
    zacc_kernel<<<dim3(B, NCHUNK), 608>>>(inputs, emb, out, beta_off);
    logits_kernel<<<B, 608>>>(lin_w, lin_b, out);
}